// round 11
// baseline (speedup 1.0000x reference)
#include <cuda_runtime.h>

// SkelConv v11: SMEM-staged swizzled x + co-in-lane broadcast consumption.
// Staging: CTA loads its x tile (iw rows x 288 floats) coalesced into SMEM,
// XOR-swizzled at 16B-chunk granularity. Hot loop: warp = 8 co-lanes x 4
// tsegs; the 8 co-lanes of a tseg read IDENTICAL SMEM addresses (broadcast),
// the 4 tsegs' chunks swizzle to distinct banks -> 1 wavefront per LDS.128.
// Weights dup'd {w,w} at [ci][q][co] (co 16B-contiguous -> 128B/1wf).
// Parity-shifted accumulators: zero pack MOVs in the hot loop.

#define C_IN   103
#define C_OUT  206
#define KK     15
#define TLEN   8192
#define NB     32
#define TPB    128
#define U      16
#define TT     256          // 4 warps * 4 tsegs * 16
#define NCH    72           // 288 floats per x row, in 16B chunks
#define RSTR   80           // padded physical chunks per row

typedef unsigned long long u64;

__device__ __forceinline__ u64 pack2(float lo, float hi) {
    u64 r;
    asm("mov.b64 %0, {%1, %2};" : "=l"(r) : "f"(lo), "f"(hi));
    return r;
}
__device__ __forceinline__ void unpack2(u64 v, float& lo, float& hi) {
    asm("mov.b64 {%0, %1}, %2;" : "=f"(lo), "=f"(hi) : "l"(v));
}
__device__ __forceinline__ void ffma2(u64& d, u64 a, u64 b) {
    asm("fma.rn.f32x2 %0, %1, %2, %0;" : "+l"(d) : "l"(a), "l"(b));
}
__device__ __forceinline__ int swz(int m) { return m ^ ((m >> 3) & 7); }

// y = 0..25: 0,1 = root halves (7 out ch each), y>=2 -> joint j=y-1 (8 out ch)
__device__ __forceinline__ void jp(int y, int& i0, int& iw, int& o0, int& ow) {
    if (y == 0)      { i0 = 0;  iw = 11; o0 = 0; ow = 7; }
    else if (y == 1) { i0 = 0;  iw = 11; o0 = 7; ow = 7; }
    else {
        const int j = y - 1;
        o0 = 14 + (j - 1) * 8; ow = 8;
        if (j == 1)       { i0 = 0;              iw = 15; }
        else if (j == 24) { i0 = 95;             iw = 8;  }
        else              { i0 = 7 + (j - 2) * 4; iw = 12; }
    }
}

__global__ void __launch_bounds__(TPB, 4)
skel_conv11_kernel(const float* __restrict__ x,
                   const float* __restrict__ w,
                   const float* __restrict__ bias,
                   const float* __restrict__ mask,
                   float* __restrict__ out)
{
    int i0, iw, o0, ow;
    jp(blockIdx.y, i0, iw, o0, ow);

    const int b     = blockIdx.z;
    const int tid   = threadIdx.x;
    const int tile0 = blockIdx.x * TT;

    __shared__ float4 xs[15 * RSTR];        // 19200 B
    __shared__ float4 wsh[15][8][8];        // 15360 B, [ci][q][co] dup'd pairs

    // ---- stage x (coalesced, bounds handled here; hot loop branch-free) ----
    {
        const float* xb = x + (size_t)b * C_IN * TLEN;
        const int total = iw * NCH;
        const int g0base = tile0 - 8;
        if (g0base >= 0 && g0base + NCH * 4 <= TLEN) {
            for (int idx = tid; idx < total; idx += TPB) {
                const int ci = idx / NCH;
                const int m  = idx - ci * NCH;
                const float4* src = reinterpret_cast<const float4*>(
                    xb + (size_t)(i0 + ci) * TLEN + g0base);
                xs[ci * RSTR + swz(m)] = src[m];
            }
        } else {
            for (int idx = tid; idx < total; idx += TPB) {
                const int ci = idx / NCH;
                const int m  = idx - ci * NCH;
                const float* xrow = xb + (size_t)(i0 + ci) * TLEN;
                const int g0 = g0base + m * 4;
                float4 v;
                v.x = (g0 + 0 >= 0 && g0 + 0 < TLEN) ? xrow[g0 + 0] : 0.0f;
                v.y = (g0 + 1 >= 0 && g0 + 1 < TLEN) ? xrow[g0 + 1] : 0.0f;
                v.z = (g0 + 2 >= 0 && g0 + 2 < TLEN) ? xrow[g0 + 2] : 0.0f;
                v.w = (g0 + 3 >= 0 && g0 + 3 < TLEN) ? xrow[g0 + 3] : 0.0f;
                xs[ci * RSTR + swz(m)] = v;
            }
        }
    }
    // ---- stage masked dup'd weights: wsh[ci][q][co] = {w2q,w2q,w2q1,w2q1} ----
    {
        const int total = iw * 64;
        for (int idx = tid; idx < total; idx += TPB) {
            const int co = idx & 7;
            const int q  = (idx >> 3) & 7;
            const int ci = idx >> 6;
            float a = 0.0f, c = 0.0f;
            if (co < ow) {
                const int gi = ((o0 + co) * C_IN + (i0 + ci)) * KK;
                a = w[gi + 2 * q] * mask[gi + 2 * q];
                if (2 * q + 1 < KK) c = w[gi + 2 * q + 1] * mask[gi + 2 * q + 1];
            }
            wsh[ci][q][co] = make_float4(a, a, c, c);
        }
    }
    __syncthreads();

    const int warp = tid >> 5;
    const int lane = tid & 31;
    const int co   = lane & 7;
    const int tseg = lane >> 3;
    const int T0   = tile0 + warp * 64 + tseg * U;

    // Precompute the 8 swizzled chunk offsets (ci-independent).
    const int mc = warp * 16 + tseg * 4;    // chunk of x[T0-8] within the row
    int moff[8];
#pragma unroll
    for (int q = 0; q < 8; q++) moff[q] = swz(mc + q);

    // accA[p]: odd taps, outputs {T0+2p, T0+2p+1}, p=0..7
    // accB[j]: even taps, outputs {T0+2j-1, T0+2j}, j=0..8
    u64 accA[8], accB[9];
#pragma unroll
    for (int p = 0; p < 8; p++) accA[p] = 0ull;
#pragma unroll
    for (int j = 0; j < 9; j++) accB[j] = 0ull;

    for (int ci = 0; ci < iw; ci++) {
        const float4* xrow4 = &xs[ci * RSTR];

        // xe[i] = {x[T0-8+2i], x[T0-8+2i+1]}, i = 0..15 (window [T0-8, T0+24))
        u64 xe[16];
#pragma unroll
        for (int q = 0; q < 8; q++) {
            const ulonglong2 v =
                *reinterpret_cast<const ulonglong2*>(&xrow4[moff[q]]);
            xe[2 * q]     = v.x;
            xe[2 * q + 1] = v.y;
        }

        const ulonglong2* wq =
            reinterpret_cast<const ulonglong2*>(&wsh[ci][0][co]);
#pragma unroll
        for (int q = 0; q < 8; q++) {
            const ulonglong2 wv = wq[q * 8];  // .x = dup w(2q), .y = dup w(2q+1)
            // even tap k=2q -> accB[j] uses xe[q+j], j=0..8
#pragma unroll
            for (int jj = 0; jj < 9; jj++) ffma2(accB[jj], wv.x, xe[q + jj]);
            // odd tap k=2q+1 (k<15) -> accA[p] uses xe[q+1+p], p=0..7
            if (q < 7) {
#pragma unroll
                for (int p = 0; p < 8; p++) ffma2(accA[p], wv.y, xe[q + 1 + p]);
            }
        }
    }

    // Combine parities + bias + store (16 outputs).
    if (co < ow) {
        const float bv = bias[o0 + co];
        float* ob = out + ((size_t)b * C_OUT + (o0 + co)) * TLEN + T0;
        float aLo[8], aHi[8], bLo[9], bHi[9];
#pragma unroll
        for (int p = 0; p < 8; p++) unpack2(accA[p], aLo[p], aHi[p]);
#pragma unroll
        for (int j = 0; j < 9; j++) unpack2(accB[j], bLo[j], bHi[j]);
#pragma unroll
        for (int p = 0; p < 8; p += 2) {
            float4 r;
            r.x = aLo[p]     + bHi[p]     + bv;   // out[T0+2p]
            r.y = aHi[p]     + bLo[p + 1] + bv;   // out[T0+2p+1]
            r.z = aLo[p + 1] + bHi[p + 1] + bv;   // out[T0+2p+2]
            r.w = aHi[p + 1] + bLo[p + 2] + bv;   // out[T0+2p+3]
            *reinterpret_cast<float4*>(ob + 2 * p) = r;
        }
    }
}

extern "C" void kernel_launch(void* const* d_in, const int* in_sizes, int n_in,
                              void* d_out, int out_size)
{
    (void)in_sizes; (void)n_in; (void)out_size;
    const float* x    = (const float*)d_in[0];
    const float* w    = (const float*)d_in[1];
    const float* bias = (const float*)d_in[2];
    const float* mask = (const float*)d_in[3];
    float* out = (float*)d_out;

    dim3 grid(TLEN / TT, 26, NB);
    skel_conv11_kernel<<<grid, TPB>>>(x, w, bias, mask, out);
}

// round 13
// speedup vs baseline: 1.2706x; 1.2706x over previous
#include <cuda_runtime.h>
#include <cuda_bf16.h>
#include <cstdint>

// SkelConv v13: tensor-core path via arch-agnostic mma.sync (HMMA), since the
// harness ptxas target is plain sm_103 (no tcgen05).
// Conv1d(K=15) = 15 tap-shifted GEMMs: D[m,co] += sum_ci A[m+tap,ci]*B_tap[ci,co]
// bf16 hi/lo split: D = Ah*Bh + Al*Bh + Ah*Bl  (error ~2^-18, fp32-grade).
// Warp tile: m16n8k16 (M=16 time, N=8 out-ch, K=16 in-ch). A in SMEM (48B row
// stride -> conflict-free ldmatrix), B fragments held in registers across the
// M-loop. 26 pseudo-joints (root 14 -> two 7-wide halves).

#define C_IN   103
#define C_OUT  206
#define KK     15
#define TLEN   8192
#define NB     32
#define TPB    128
#define CTAT   256          // time per CTA: 4 warps * 4 mtiles * 16
#define NROW   272          // 256 + 14 halo, padded to 272
#define RST    24           // row stride in bf16 elems (48 B)

// y = 0..25: 0,1 = root halves (7 out ch each), y>=2 -> joint j=y-1 (8 out ch)
__device__ __forceinline__ void jp(int y, int& i0, int& iw, int& o0, int& ow) {
    if (y == 0)      { i0 = 0;  iw = 11; o0 = 0; ow = 7; }
    else if (y == 1) { i0 = 0;  iw = 11; o0 = 7; ow = 7; }
    else {
        const int j = y - 1;
        o0 = 14 + (j - 1) * 8; ow = 8;
        if (j == 1)       { i0 = 0;              iw = 15; }
        else if (j == 24) { i0 = 95;             iw = 8;  }
        else              { i0 = 7 + (j - 2) * 4; iw = 12; }
    }
}

__device__ __forceinline__ uint32_t s2u(const void* p) {
    uint32_t a;
    asm("{ .reg .u64 t; cvta.to.shared.u64 t, %1; cvt.u32.u64 %0, t; }"
        : "=r"(a) : "l"(p));
    return a;
}

__device__ __forceinline__ void ldmat4(uint32_t& r0, uint32_t& r1,
                                       uint32_t& r2, uint32_t& r3,
                                       uint32_t addr) {
    asm volatile("ldmatrix.sync.aligned.m8n8.x4.shared.b16 {%0,%1,%2,%3}, [%4];"
                 : "=r"(r0), "=r"(r1), "=r"(r2), "=r"(r3) : "r"(addr));
}

__device__ __forceinline__ void mma16816(float& d0, float& d1, float& d2, float& d3,
                                         uint32_t a0, uint32_t a1, uint32_t a2,
                                         uint32_t a3, uint32_t b0, uint32_t b1) {
    asm volatile(
        "mma.sync.aligned.m16n8k16.row.col.f32.bf16.bf16.f32 "
        "{%0,%1,%2,%3}, {%4,%5,%6,%7}, {%8,%9}, {%0,%1,%2,%3};"
        : "+f"(d0), "+f"(d1), "+f"(d2), "+f"(d3)
        : "r"(a0), "r"(a1), "r"(a2), "r"(a3), "r"(b0), "r"(b1));
}

__device__ __forceinline__ uint32_t pkbf2(float lo, float hi) {
    __nv_bfloat16 l = __float2bfloat16(lo);
    __nv_bfloat16 h = __float2bfloat16(hi);
    uint16_t lu = *reinterpret_cast<uint16_t*>(&l);
    uint16_t hu = *reinterpret_cast<uint16_t*>(&h);
    return (uint32_t)lu | ((uint32_t)hu << 16);
}

__global__ void __launch_bounds__(TPB, 4)
skel_hmma_kernel(const float* __restrict__ x,
                 const float* __restrict__ w,
                 const float* __restrict__ bias,
                 const float* __restrict__ mask,
                 float* __restrict__ out)
{
    int i0, iw, o0, ow;
    jp(blockIdx.y, i0, iw, o0, ow);

    const int b     = blockIdx.z;
    const int tile0 = blockIdx.x * CTAT;
    const int tid   = threadIdx.x;
    const int wid   = tid >> 5;
    const int lane  = tid & 31;

    // A tiles: xs[row][ci], row = time tile0-7+row, 48B row stride.
    __shared__ __nv_bfloat16 xsh[NROW * RST];          // 13056 B
    __shared__ __nv_bfloat16 xsl[NROW * RST];          // 13056 B
    // B frags: [tap][kp(8)][co(8)] bf16x2 = {B[2kp][co], B[2kp+1][co]}
    __shared__ uint32_t bsh[KK * 64];                  // 3840 B
    __shared__ uint32_t bsl[KK * 64];                  // 3840 B

    // ---- stage x (hi/lo split), coalesced per-ci rows ----
    for (int ci = 0; ci < 16; ci++) {
        const float* xrow = x + ((size_t)b * C_IN + (i0 + ci)) * TLEN;
        const bool civ = (ci < iw);
        for (int r = tid; r < NROW; r += TPB) {
            const int t = tile0 - 7 + r;
            float v = (civ && t >= 0 && t < TLEN) ? xrow[t] : 0.0f;
            __nv_bfloat16 h = __float2bfloat16(v);
            __nv_bfloat16 l = __float2bfloat16(v - __bfloat162float(h));
            xsh[r * RST + ci] = h;
            xsl[r * RST + ci] = l;
        }
    }
    // ---- stage masked weights (hi/lo) as B fragments ----
    for (int idx = tid; idx < KK * 64; idx += TPB) {
        const int tap = idx >> 6;
        const int kp  = (idx >> 3) & 7;
        const int co  = idx & 7;
        float v0 = 0.0f, v1 = 0.0f;
        if (co < ow) {
            const int ci0 = 2 * kp, ci1 = 2 * kp + 1;
            if (ci0 < iw) {
                const int gi = ((o0 + co) * C_IN + (i0 + ci0)) * KK + tap;
                v0 = w[gi] * mask[gi];
            }
            if (ci1 < iw) {
                const int gi = ((o0 + co) * C_IN + (i0 + ci1)) * KK + tap;
                v1 = w[gi] * mask[gi];
            }
        }
        __nv_bfloat16 h0 = __float2bfloat16(v0);
        __nv_bfloat16 h1 = __float2bfloat16(v1);
        bsh[idx] = pkbf2(__bfloat162float(h0), __bfloat162float(h1));
        bsl[idx] = pkbf2(v0 - __bfloat162float(h0), v1 - __bfloat162float(h1));
    }
    __syncthreads();

    // ---- per-lane B fragment registers (held across M-loop) ----
    const int gid = lane >> 2;      // 0..7  (n / row-group)
    const int tig = lane & 3;       // 0..3
    uint32_t bh0[KK], bh1[KK], bl0[KK], bl1[KK];
#pragma unroll
    for (int tap = 0; tap < KK; tap++) {
        const int base = tap * 64 + tig * 8 + gid;
        bh0[tap] = bsh[base];
        bh1[tap] = bsh[base + 32];
        bl0[tap] = bsl[base];
        bl1[tap] = bsl[base + 32];
    }

    // ldmatrix per-lane address components
    const int tsel   = lane >> 3;                   // tile 0..3
    const int rowoff = (lane & 7) + ((tsel & 1) << 3);
    const int coloff = (tsel >> 1) << 4;            // +16B for ci 8..15
    const uint32_t ah_base = s2u(xsh) + (uint32_t)(rowoff * 48 + coloff);
    const uint32_t al_base = s2u(xsl) + (uint32_t)(rowoff * 48 + coloff);

    const float bias0 = (2 * tig < ow)     ? bias[o0 + 2 * tig]     : 0.0f;
    const float bias1 = (2 * tig + 1 < ow) ? bias[o0 + 2 * tig + 1] : 0.0f;
    float* ob = out + (size_t)b * C_OUT * TLEN;

#pragma unroll
    for (int mt = 0; mt < 4; mt++) {
        const int rbase = (wid * 4 + mt) * 16;      // A row base (tap 0)
        const int T0    = tile0 + rbase;
        float d0 = 0.0f, d1 = 0.0f, d2 = 0.0f, d3 = 0.0f;

        uint32_t ah = ah_base + (uint32_t)(rbase * 48);
        uint32_t al = al_base + (uint32_t)(rbase * 48);

#pragma unroll
        for (int tap = 0; tap < KK; tap++) {
            uint32_t h0, h1, h2, h3, l0, l1, l2, l3;
            ldmat4(h0, h1, h2, h3, ah);
            ldmat4(l0, l1, l2, l3, al);
            mma16816(d0, d1, d2, d3, h0, h1, h2, h3, bh0[tap], bh1[tap]);
            mma16816(d0, d1, d2, d3, l0, l1, l2, l3, bh0[tap], bh1[tap]);
            mma16816(d0, d1, d2, d3, h0, h1, h2, h3, bl0[tap], bl1[tap]);
            ah += 48;
            al += 48;
        }

        // D mapping: d0=(row=gid, n=2tig), d1=(gid, 2tig+1),
        //            d2=(gid+8, 2tig), d3=(gid+8, 2tig+1)
        const int t0r = T0 + gid;
        if (2 * tig < ow) {
            float* p = ob + (size_t)(o0 + 2 * tig) * TLEN;
            p[t0r]     = d0 + bias0;
            p[t0r + 8] = d2 + bias0;
        }
        if (2 * tig + 1 < ow) {
            float* p = ob + (size_t)(o0 + 2 * tig + 1) * TLEN;
            p[t0r]     = d1 + bias1;
            p[t0r + 8] = d3 + bias1;
        }
    }
}

extern "C" void kernel_launch(void* const* d_in, const int* in_sizes, int n_in,
                              void* d_out, int out_size)
{
    (void)in_sizes; (void)n_in; (void)out_size;
    const float* x    = (const float*)d_in[0];
    const float* w    = (const float*)d_in[1];
    const float* bias = (const float*)d_in[2];
    const float* mask = (const float*)d_in[3];
    float* out = (float*)d_out;

    dim3 grid(TLEN / CTAT, 26, NB);
    skel_hmma_kernel<<<grid, TPB>>>(x, w, bias, mask, out);
}